// round 15
// baseline (speedup 1.0000x reference)
#include <cuda_runtime.h>
#include <cuda_bf16.h>
#include <stdint.h>

#define C_IN   32
#define C_OUT  32
#define KD     27
#define TPB    128
#define TM     128
#define MAXN   262144
#define ARS    144                   // A row stride (bytes): conflict-free ldsm

// dynamic smem layout (bytes)
#define OFF_A(st)  ((st) * (TM * ARS))            // 2 x 18432
#define OFF_SIDX   (2 * TM * ARS)                 // 128*27*4 = 13824
#define SMEM_TOTAL (OFF_SIDX + TM * KD * 4)       // 50688

// ---------------- device scratch ----------------
__device__ __align__(256) __nv_bfloat16 g_pack[(MAXN + 1) * 64]; // [N+1][128B] hi|lo; row N zeros
__device__ __align__(256) uint2 g_bfrag[KD * 16 * 32];           // [k][frag][lane], 4KB/k
__device__ int g_neigh_is64;

// ---------------- helpers ----------------
__device__ __forceinline__ uint32_t s2u(const void* p) {
    uint32_t a;
    asm("{ .reg .u64 t; cvta.to.shared.u64 t, %1; cvt.u32.u64 %0, t; }" : "=r"(a) : "l"(p));
    return a;
}
__device__ __forceinline__ void cpasync16(uint32_t dst, const void* src) {
    asm volatile("cp.async.cg.shared.global [%0], [%1], 16;" :: "r"(dst), "l"(src));
}
__device__ __forceinline__ void ldsm4(uint32_t* r, uint32_t addr) {
    asm volatile("ldmatrix.sync.aligned.m8n8.x4.shared.b16 {%0,%1,%2,%3}, [%4];"
                 : "=r"(r[0]), "=r"(r[1]), "=r"(r[2]), "=r"(r[3]) : "r"(addr));
}
__device__ __forceinline__ void mma16816(float* c, const uint32_t* a, uint2 b) {
    asm volatile("mma.sync.aligned.m16n8k16.row.col.f32.bf16.bf16.f32 "
                 "{%0,%1,%2,%3}, {%4,%5,%6,%7}, {%8,%9}, {%0,%1,%2,%3};"
                 : "+f"(c[0]), "+f"(c[1]), "+f"(c[2]), "+f"(c[3])
                 : "r"(a[0]), "r"(a[1]), "r"(a[2]), "r"(a[3]), "r"(b.x), "r"(b.y));
}

// ---------------- pre-pass: dtype detect ----------------
__global__ void detect_dtype_kernel(const int* __restrict__ w, long long n_words32) {
    __shared__ int ok;
    if (threadIdx.x == 0) ok = 1;
    __syncthreads();
    const long long pos = 2LL * threadIdx.x + 1;
    if (pos < n_words32) {
        const int v = w[pos];
        if (v != 0 && v != -1) ok = 0;
    }
    __syncthreads();
    if (threadIdx.x == 0) g_neigh_is64 = ok;
}

// ---------------- pre-pass: data -> packed hi|lo bf16 rows (+ zero pad row) ----------------
__global__ void convert_data_kernel(const float* __restrict__ data, int nrows) {
    const int i = blockIdx.x * blockDim.x + threadIdx.x;   // chunk id: row*8 + c
    if (i >= (nrows + 1) * 8) return;
    const int row = i >> 3, c = i & 7;
    if (row == nrows) {
        *(uint4*)(g_pack + (long long)row * 64 + c * 8) = make_uint4(0, 0, 0, 0);
        return;
    }
    const bool lo = (c >= 4);
    const int e0  = (c & 3) * 8;
    const float4* s = (const float4*)(data + (long long)row * C_IN + e0);
    const float4 f0 = s[0], f1 = s[1];
    const float v[8] = { f0.x, f0.y, f0.z, f0.w, f1.x, f1.y, f1.z, f1.w };
    __nv_bfloat16 h[8];
    #pragma unroll
    for (int j = 0; j < 8; j++) {
        const __nv_bfloat16 hh = __float2bfloat16(v[j]);
        h[j] = lo ? __float2bfloat16(v[j] - __bfloat162float(hh)) : hh;
    }
    *(uint4*)(g_pack + (long long)row * 64 + c * 8) = *(const uint4*)h;
}

// ---------------- pre-pass: weights -> B fragments (m16n8k16 layout) ----------------
__global__ void convert_bfrag_kernel(const float* __restrict__ w) {
    const int i = blockIdx.x * blockDim.x + threadIdx.x;   // (k, f, lane)
    if (i >= KD * 16 * 32) return;
    const int lane = i & 31, f = (i >> 5) & 15, k = i >> 9;
    const int nt = f & 3, s = (f >> 2) & 1, v = f >> 3;
    const int n  = nt * 8 + (lane >> 2);
    const int r0 = (lane & 3) * 2;
    const int rows[4] = { r0, r0 + 1, r0 + 8, r0 + 9 };
    uint16_t h[4];
    #pragma unroll
    for (int j = 0; j < 4; j++) {
        const float x = w[k * C_IN * C_OUT + (s * 16 + rows[j]) * C_OUT + n];
        const __nv_bfloat16 hi = __float2bfloat16(x);
        const __nv_bfloat16 val = (v == 0) ? hi : __float2bfloat16(x - __bfloat162float(hi));
        h[j] = *(const uint16_t*)&val;
    }
    uint2 r;
    r.x = (uint32_t)h[0] | ((uint32_t)h[1] << 16);
    r.y = (uint32_t)h[2] | ((uint32_t)h[3] << 16);
    g_bfrag[(k * 16 + f) * 32 + lane] = r;
}

// ---------------- main: warp-local cp.async gather + reg-B + HMMA 3xBF16 ----------------
__global__ __launch_bounds__(TPB, 4) void octconv_hmma_kernel(
    const void* __restrict__ neigh_raw, float* __restrict__ out, int N)
{
    extern __shared__ __align__(256) uint8_t smem[];

    const int tid  = threadIdx.x;
    const int warp = tid >> 5;
    const int lane = tid & 31;
    const int base = blockIdx.x * TM;
    const bool is64 = (g_neigh_is64 != 0);
    const int*       n32 = (const int*)neigh_raw;
    const long long* n64 = (const long long*)neigh_raw;

    const uint32_t smemb  = s2u(smem);
    const uint32_t aAddr[2] = { smemb + OFF_A(0), smemb + OFF_A(1) };
    int* sidx = (int*)(smem + OFF_SIDX);           // [k][row], pre-shifted <<7

    // ---- coalesced index staging ----
    {
        const long long lim = (long long)N * KD;
        #pragma unroll
        for (int i = tid; i < TM * KD; i += TPB) {
            const long long e = (long long)base * KD + i;
            int v = -1;
            if (e < lim) v = is64 ? (int)n64[e] : n32[e];
            const int row = i / KD, k = i - row * KD;
            sidx[k * TM + row] = ((v >= 0 && v < N) ? v : N) << 7;
        }
    }
    __syncthreads();

    const uint8_t* packb = (const uint8_t*)g_pack;
    const int c16 = (lane & 7) * 16;               // 16B chunk within row
    const int sub = lane >> 3;                     // 0..3: row within 4-row group

    // A issue: 8 warp-level cp.async; each covers 4 full rows (8 lanes/row)
    #define ISSUE_A(kk) do {                                                         \
        const uint32_t ab_ = aAddr[(kk) & 1];                                        \
        const int* sk_ = sidx + (kk) * TM + warp * 32 + sub;                         \
        _Pragma("unroll")                                                            \
        for (int j_ = 0; j_ < 8; j_++) {                                             \
            const int row_ = warp * 32 + 4 * j_ + sub;                               \
            const uint32_t off_ = (uint32_t)sk_[4 * j_];     /* LDS broadcast */     \
            cpasync16(ab_ + row_ * ARS + c16, packb + off_ + c16);                   \
        }                                                                            \
        asm volatile("cp.async.commit_group;");                                      \
    } while (0)

    float acc[2][4][4];
    #pragma unroll
    for (int mt = 0; mt < 2; mt++)
        #pragma unroll
        for (int nt = 0; nt < 4; nt++)
            #pragma unroll
            for (int e = 0; e < 4; e++) acc[mt][nt][e] = 0.0f;

    ISSUE_A(0);

    for (int k = 0; k < KD; k++) {
        const int b = k & 1;
        if (k + 1 < KD) ISSUE_A(k + 1);            // own rows of buf b^1 (read at k-1)

        // B fragments for k -> registers (L2-hot LDG.64, latency overlaps A-wait)
        uint2 bfr[16];
        {
            const uint2* bsrc = g_bfrag + k * 16 * 32 + lane;
            #pragma unroll
            for (int f = 0; f < 16; f++) bfr[f] = bsrc[f * 32];
        }

        if (k + 1 < KD) { asm volatile("cp.async.wait_group 1;" ::: "memory"); }
        else            { asm volatile("cp.async.wait_group 0;" ::: "memory"); }
        __syncthreads();                            // cross-lane visibility of A_k

        #pragma unroll
        for (int mt = 0; mt < 2; mt++) {
            const uint32_t rowoff = (uint32_t)((warp * 32 + mt * 16 + (lane & 15)) * ARS
                                               + ((lane >> 4) << 4));
            uint32_t ah0[4], ah1[4], al0[4], al1[4];
            ldsm4(ah0, aAddr[b] + rowoff + 0);     // hi, kstep0
            ldsm4(ah1, aAddr[b] + rowoff + 32);    // hi, kstep1
            ldsm4(al0, aAddr[b] + rowoff + 64);    // lo, kstep0
            ldsm4(al1, aAddr[b] + rowoff + 96);    // lo, kstep1
            #pragma unroll
            for (int nt = 0; nt < 4; nt++) {
                mma16816(acc[mt][nt], ah0, bfr[0 + nt]);    // hi*whi s0
                mma16816(acc[mt][nt], ah1, bfr[4 + nt]);    // hi*whi s1
                mma16816(acc[mt][nt], ah0, bfr[8 + nt]);    // hi*wlo s0
                mma16816(acc[mt][nt], ah1, bfr[12 + nt]);   // hi*wlo s1
                mma16816(acc[mt][nt], al0, bfr[0 + nt]);    // lo*whi s0
                mma16816(acc[mt][nt], al1, bfr[4 + nt]);    // lo*whi s1
            }
        }
        // no trailing barrier: A rows are warp-private (writer == reader warp)
    }
    __syncthreads();

    // ---- epilogue: C frags -> smem [128][34] -> coalesced store (warp-private rows) ----
    float* sg = (float*)smem;
    #pragma unroll
    for (int mt = 0; mt < 2; mt++) {
        const int r = warp * 32 + mt * 16 + (lane >> 2);
        #pragma unroll
        for (int nt = 0; nt < 4; nt++) {
            const int c = nt * 8 + (lane & 3) * 2;
            *(float2*)(sg + r * 34 + c)       = make_float2(acc[mt][nt][0], acc[mt][nt][1]);
            *(float2*)(sg + (r + 8) * 34 + c) = make_float2(acc[mt][nt][2], acc[mt][nt][3]);
        }
    }
    __syncwarp();
    #pragma unroll 4
    for (int i = 0; i < 32; i++) {
        const int r = warp * 32 + i;
        const int node = base + r;
        if (node < N) out[(long long)node * C_OUT + lane] = sg[r * 34 + lane];
    }
}

extern "C" void kernel_launch(void* const* d_in, const int* in_sizes, int n_in,
                              void* d_out, int out_size)
{
    // Identify inputs by element count: weights=27648 (smallest); data=N*32 (largest); neigh=N*27
    long long s[3] = { (long long)in_sizes[0], (long long)in_sizes[1], (long long)in_sizes[2] };
    int iw  = (s[0] <= s[1] && s[0] <= s[2]) ? 0 : (s[1] <= s[2] ? 1 : 2);
    int idt = (s[0] >= s[1] && s[0] >= s[2]) ? 0 : (s[1] >= s[2] ? 1 : 2);
    if (iw == idt) { iw = 1; idt = 0; }
    int ing = 3 - iw - idt;

    const float* data    = (const float*)d_in[idt];
    const float* weights = (const float*)d_in[iw];
    const void*  neigh   = d_in[ing];
    float*       out     = (float*)d_out;

    const int N = (int)(s[idt] / C_IN);

    static int smem_set = 0;
    if (!smem_set) {
        cudaFuncSetAttribute(octconv_hmma_kernel,
                             cudaFuncAttributeMaxDynamicSharedMemorySize, SMEM_TOTAL);
        smem_set = 1;
    }

    detect_dtype_kernel<<<1, 1024>>>((const int*)neigh, s[ing]);
    convert_data_kernel<<<((N + 1) * 8 + 255) / 256, 256>>>(data, N);
    convert_bfrag_kernel<<<(KD * 16 * 32 + 255) / 256, 256>>>(weights);
    octconv_hmma_kernel<<<(N + TM - 1) / TM, TPB, SMEM_TOTAL>>>(neigh, out, N);
}

// round 16
// speedup vs baseline: 2.7819x; 2.7819x over previous
#include <cuda_runtime.h>
#include <cuda_fp16.h>
#include <stdint.h>

#define C_IN   32
#define C_OUT  32
#define KD     27
#define TPB    128
#define TM     128
#define MAXN   262144
#define ARS    80                    // A row stride (bytes): 64B row + 16 pad, conflict-free ldsm
#define STAGE_TX (TM * 64 + 4096)    // A 8KB + B 4KB per stage

// ---------------- device scratch ----------------
__device__ __align__(256) __half g_pack[(MAXN + 1) * 32];   // [N+1][64B] fp16 rows; row N zeros
__device__ __align__(256) uint2 g_bfrag[KD * 16 * 32];      // [k][frag][lane]: fp16 hi/lo W frags
__device__ int g_neigh_is64;

// ---------------- helpers ----------------
__device__ __forceinline__ uint32_t s2u(const void* p) {
    uint32_t a;
    asm("{ .reg .u64 t; cvta.to.shared.u64 t, %1; cvt.u32.u64 %0, t; }" : "=r"(a) : "l"(p));
    return a;
}
__device__ __forceinline__ void bulkcp(uint32_t dst, const void* src, uint32_t bytes, uint32_t mbar) {
    asm volatile("cp.async.bulk.shared::cluster.global.mbarrier::complete_tx::bytes "
                 "[%0], [%1], %2, [%3];"
                 :: "r"(dst), "l"(src), "r"(bytes), "r"(mbar) : "memory");
}
__device__ __forceinline__ void ldsm4(uint32_t* r, uint32_t addr) {
    asm volatile("ldmatrix.sync.aligned.m8n8.x4.shared.b16 {%0,%1,%2,%3}, [%4];"
                 : "=r"(r[0]), "=r"(r[1]), "=r"(r[2]), "=r"(r[3]) : "r"(addr));
}
__device__ __forceinline__ void mma16816(float* c, const uint32_t* a, uint2 b) {
    asm volatile("mma.sync.aligned.m16n8k16.row.col.f32.f16.f16.f32 "
                 "{%0,%1,%2,%3}, {%4,%5,%6,%7}, {%8,%9}, {%0,%1,%2,%3};"
                 : "+f"(c[0]), "+f"(c[1]), "+f"(c[2]), "+f"(c[3])
                 : "r"(a[0]), "r"(a[1]), "r"(a[2]), "r"(a[3]), "r"(b.x), "r"(b.y));
}
#define MBAR_WAIT(addr, ph) do {                                                      \
    asm volatile("{\n\t.reg .pred P1;\n\t"                                            \
        "WAIT_%=:\n\t"                                                                \
        "mbarrier.try_wait.parity.acquire.cta.shared::cta.b64 P1, [%0], %1, 0x989680;\n\t" \
        "@P1 bra.uni DONE_%=;\n\t"                                                    \
        "bra.uni WAIT_%=;\n\t"                                                        \
        "DONE_%=:\n\t}"                                                               \
        :: "r"(addr), "r"((uint32_t)(ph)) : "memory"); } while (0)

// ---------------- pre-pass: dtype detect ----------------
__global__ void detect_dtype_kernel(const int* __restrict__ w, long long n_words32) {
    __shared__ int ok;
    if (threadIdx.x == 0) ok = 1;
    __syncthreads();
    const long long pos = 2LL * threadIdx.x + 1;
    if (pos < n_words32) {
        const int v = w[pos];
        if (v != 0 && v != -1) ok = 0;
    }
    __syncthreads();
    if (threadIdx.x == 0) g_neigh_is64 = ok;
}

// ---------------- pre-pass: data -> fp16 rows (64B) + zero pad row ----------------
__global__ void convert_data_kernel(const float* __restrict__ data, int nrows) {
    const int i = blockIdx.x * blockDim.x + threadIdx.x;   // chunk id: row*4 + c (16B chunks)
    if (i >= (nrows + 1) * 4) return;
    const int row = i >> 2, c = i & 3;
    if (row == nrows) {
        *(uint4*)(g_pack + (long long)row * 32 + c * 8) = make_uint4(0, 0, 0, 0);
        return;
    }
    const float4* s = (const float4*)(data + (long long)row * C_IN + c * 8);
    const float4 f0 = s[0], f1 = s[1];
    const float v[8] = { f0.x, f0.y, f0.z, f0.w, f1.x, f1.y, f1.z, f1.w };
    __half h[8];
    #pragma unroll
    for (int j = 0; j < 8; j++) h[j] = __float2half(v[j]);
    *(uint4*)(g_pack + (long long)row * 32 + c * 8) = *(const uint4*)h;
}

// ---------------- pre-pass: weights -> fp16 hi/lo B fragments (m16n8k16 layout) ----------------
__global__ void convert_bfrag_kernel(const float* __restrict__ w) {
    const int i = blockIdx.x * blockDim.x + threadIdx.x;   // (k, f, lane)
    if (i >= KD * 16 * 32) return;
    const int lane = i & 31, f = (i >> 5) & 15, k = i >> 9;
    const int nt = f & 3, s = (f >> 2) & 1, v = f >> 3;    // v: 0=hi, 1=lo
    const int n  = nt * 8 + (lane >> 2);
    const int r0 = (lane & 3) * 2;
    const int rows[4] = { r0, r0 + 1, r0 + 8, r0 + 9 };
    uint16_t h[4];
    #pragma unroll
    for (int j = 0; j < 4; j++) {
        const float x = w[k * C_IN * C_OUT + (s * 16 + rows[j]) * C_OUT + n];
        const __half hi = __float2half(x);
        const __half val = (v == 0) ? hi : __float2half(x - __half2float(hi));
        h[j] = *(const uint16_t*)&val;
    }
    uint2 r;
    r.x = (uint32_t)h[0] | ((uint32_t)h[1] << 16);
    r.y = (uint32_t)h[2] | ((uint32_t)h[3] << 16);
    g_bfrag[(k * 16 + f) * 32 + lane] = r;
}

// ---------------- main: bulk-gather (64B rows) + HMMA fp16, leader-wait pipeline ----------------
__global__ __launch_bounds__(TPB) void octconv_hmma_kernel(
    const void* __restrict__ neigh_raw, float* __restrict__ out, int N)
{
    __shared__ __align__(256) uint8_t sA[2][TM * ARS];      // 20.5KB A tiles
    __shared__ __align__(256) uint8_t sB[2][4096];          // 8KB  B fragment blobs
    __shared__ __align__(8)  uint64_t smbar[2];

    const int tid  = threadIdx.x;
    const int warp = tid >> 5;
    const int lane = tid & 31;
    const int base = blockIdx.x * TM;
    const bool is64 = (g_neigh_is64 != 0);
    const int*       n32 = (const int*)neigh_raw;
    const long long* n64 = (const long long*)neigh_raw;

    const uint32_t aAddr[2] = { s2u(&sA[0][0]), s2u(&sA[1][0]) };
    const uint32_t bAddr[2] = { s2u(&sB[0][0]), s2u(&sB[1][0]) };
    const uint32_t mAddr[2] = { s2u(&smbar[0]), s2u(&smbar[1]) };

    if (tid == 0) {
        asm volatile("mbarrier.init.shared.b64 [%0], %1;" :: "r"(mAddr[0]), "r"(1u) : "memory");
        asm volatile("mbarrier.init.shared.b64 [%0], %1;" :: "r"(mAddr[1]), "r"(1u) : "memory");
    }

    // ---- coalesced index staging through sA (free pre-pipeline; 13824B < 20480B) ----
    {
        int* tmp = (int*)&sA[0][0];
        const long long lim = (long long)N * KD;
        #pragma unroll
        for (int i = tid; i < TM * KD; i += TPB) {
            const long long e = (long long)base * KD + i;
            int v = -1;
            if (e < lim) v = is64 ? (int)n64[e] : n32[e];
            tmp[i] = ((v >= 0 && v < N) ? v : N) << 6;     // byte offset into g_pack (64B rows)
        }
        __syncthreads();
    }
    uint32_t aoff[KD];                                     // per-thread source offsets
    {
        const int* tmp = (const int*)&sA[0][0];
        #pragma unroll
        for (int j = 0; j < KD; j++) aoff[j] = (uint32_t)tmp[tid * KD + j];
        __syncthreads();                                   // done reading before bulk writes
    }

    float acc[2][4][4];
    #pragma unroll
    for (int mt = 0; mt < 2; mt++)
        #pragma unroll
        for (int nt = 0; nt < 4; nt++)
            #pragma unroll
            for (int e = 0; e < 4; e++) acc[mt][nt][e] = 0.0f;

    const uint8_t* packb = (const uint8_t*)g_pack;
    const uint32_t myDst[2] = { aAddr[0] + tid * ARS, aAddr[1] + tid * ARS };

    #define ISSUE(k) do {                                                            \
        const int b_ = (k) & 1;                                                      \
        if (tid == 0) {                                                              \
            asm volatile("mbarrier.arrive.expect_tx.shared.b64 _, [%0], %1;"         \
                         :: "r"(mAddr[b_]), "r"((uint32_t)STAGE_TX) : "memory");     \
            bulkcp(bAddr[b_], (const uint8_t*)g_bfrag + (k) * 4096, 4096, mAddr[b_]);\
        }                                                                            \
        bulkcp(myDst[b_], packb + aoff[(k)], 64, mAddr[b_]);                         \
    } while (0)

    ISSUE(0);
    int ph0 = 0, ph1 = 0;

    for (int k = 0; k < KD; k++) {
        const int b = k & 1;
        if (k + 1 < KD) ISSUE(k + 1);          // buffer b^1 freed by last iter's end-sync
        if (warp == 0) {                       // leader-wait: only warp 0 polls
            if (b == 0) { MBAR_WAIT(mAddr[0], ph0); }
            else        { MBAR_WAIT(mAddr[1], ph1); }
        }
        if (b == 0) ph0 ^= 1; else ph1 ^= 1;
        __syncthreads();                       // others stall cheaply on BAR

        const uint2* bf = (const uint2*)(&sB[b][0]);
        #pragma unroll
        for (int mt = 0; mt < 2; mt++) {
            const uint32_t rowoff = (uint32_t)((warp * 32 + mt * 16 + (lane & 15)) * ARS
                                               + ((lane >> 4) << 4));
            uint32_t a0[4], a1[4];
            ldsm4(a0, aAddr[b] + rowoff + 0);     // kstep0 (bytes 0-31)
            ldsm4(a1, aAddr[b] + rowoff + 32);    // kstep1 (bytes 32-63)
            #pragma unroll
            for (int nt = 0; nt < 4; nt++) {
                const uint2 bh0 = bf[(0 + nt)  * 32 + lane];   // whi, s0
                const uint2 bh1 = bf[(4 + nt)  * 32 + lane];   // whi, s1
                const uint2 bl0 = bf[(8 + nt)  * 32 + lane];   // wlo, s0
                const uint2 bl1 = bf[(12 + nt) * 32 + lane];   // wlo, s1
                mma16816(acc[mt][nt], a0, bh0);   // a*whi
                mma16816(acc[mt][nt], a1, bh1);
                mma16816(acc[mt][nt], a0, bl0);   // a*wlo
                mma16816(acc[mt][nt], a1, bl1);
            }
        }
        __syncthreads();   // buffer b consumed -> free for k+2
    }

    // ---- epilogue: C frags -> smem [128][34] -> coalesced store (17408B < 20480B) ----
    float* sg = (float*)&sA[0][0];
    #pragma unroll
    for (int mt = 0; mt < 2; mt++) {
        const int r = warp * 32 + mt * 16 + (lane >> 2);
        #pragma unroll
        for (int nt = 0; nt < 4; nt++) {
            const int c = nt * 8 + (lane & 3) * 2;
            *(float2*)(sg + r * 34 + c)       = make_float2(acc[mt][nt][0], acc[mt][nt][1]);
            *(float2*)(sg + (r + 8) * 34 + c) = make_float2(acc[mt][nt][2], acc[mt][nt][3]);
        }
    }
    __syncthreads();
    #pragma unroll 4
    for (int i = 0; i < 32; i++) {
        const int r = warp * 32 + i;
        const int node = base + r;
        if (node < N) out[(long long)node * C_OUT + lane] = sg[r * 34 + lane];
    }
}

extern "C" void kernel_launch(void* const* d_in, const int* in_sizes, int n_in,
                              void* d_out, int out_size)
{
    // Identify inputs by element count: weights=27648 (smallest); data=N*32 (largest); neigh=N*27
    long long s[3] = { (long long)in_sizes[0], (long long)in_sizes[1], (long long)in_sizes[2] };
    int iw  = (s[0] <= s[1] && s[0] <= s[2]) ? 0 : (s[1] <= s[2] ? 1 : 2);
    int idt = (s[0] >= s[1] && s[0] >= s[2]) ? 0 : (s[1] >= s[2] ? 1 : 2);
    if (iw == idt) { iw = 1; idt = 0; }
    int ing = 3 - iw - idt;

    const float* data    = (const float*)d_in[idt];
    const float* weights = (const float*)d_in[iw];
    const void*  neigh   = d_in[ing];
    float*       out     = (float*)d_out;

    const int N = (int)(s[idt] / C_IN);

    detect_dtype_kernel<<<1, 1024>>>((const int*)neigh, s[ing]);
    convert_data_kernel<<<((N + 1) * 4 + 255) / 256, 256>>>(data, N);
    convert_bfrag_kernel<<<(KD * 16 * 32 + 255) / 256, 256>>>(weights);
    octconv_hmma_kernel<<<(N + TM - 1) / TM, TPB>>>(neigh, out, N);
}